// round 7
// baseline (speedup 1.0000x reference)
#include <cuda_runtime.h>
#include <math.h>
#include <cstdint>

#define MTOT 8192
#define NHALF 4096
#define DDIM 128
#define BM 128
#define BN 128
#define TM 8
#define TN 8
#define NBLOCKS 2080            // 64*65/2 upper-triangle tiles
#define LDA 132                 // smem row stride (floats)
#define SMEM_BYTES (2 * DDIM * LDA * 4)

typedef unsigned long long u64;

__device__ float  g_sq[MTOT];
__device__ float  g_v[DDIM];
__device__ float  g_S;
__device__ float  g_c2l;        // c * log2(e):  t = exp(-c*L2) = exp2(-c2l*L2)
__device__ double g_acc;

// ---- packed f32x2 helpers (PTX ISA 8.6, plain sm_100+; NOT 'a'-gated) ----
__device__ __forceinline__ void ffma2(u64& d, u64 a, u64 b) {
    asm("fma.rn.f32x2 %0, %1, %2, %0;" : "+l"(d) : "l"(a), "l"(b));
}
__device__ __forceinline__ u64 dup2(float x) {
    u64 r; asm("mov.b64 %0, {%1, %1};" : "=l"(r) : "f"(x)); return r;
}
__device__ __forceinline__ void unpack2(float& lo, float& hi, u64 v) {
    asm("mov.b64 {%0, %1}, %2;" : "=f"(lo), "=f"(hi) : "l"(v));
}

__global__ void k_init() {
    int t = threadIdx.x;
    if (t < DDIM) g_v[t] = 0.f;
    if (t == 0) { g_S = 0.f; g_acc = 0.0; }
}

__global__ void k_rows(const float* __restrict__ src, const float* __restrict__ tgt) {
    __shared__ float cs[DDIM];
    __shared__ float ss;
    int warp = threadIdx.x >> 5, lane = threadIdx.x & 31;
    int row = blockIdx.x * 8 + warp;
    const float* p = (row < NHALF) ? (src + (size_t)row * DDIM)
                                   : (tgt + (size_t)(row - NHALF) * DDIM);
    float4 x = ((const float4*)p)[lane];
    float s = x.x*x.x + x.y*x.y + x.z*x.z + x.w*x.w;
    if (threadIdx.x < DDIM) cs[threadIdx.x] = 0.f;
    if (threadIdx.x == 0) ss = 0.f;
    __syncthreads();
    atomicAdd(&cs[lane*4+0], x.x); atomicAdd(&cs[lane*4+1], x.y);
    atomicAdd(&cs[lane*4+2], x.z); atomicAdd(&cs[lane*4+3], x.w);
    #pragma unroll
    for (int o = 16; o; o >>= 1) s += __shfl_xor_sync(0xffffffffu, s, o);
    if (lane == 0) { g_sq[row] = s; atomicAdd(&ss, s); }
    __syncthreads();
    if (threadIdx.x < DDIM) atomicAdd(&g_v[threadIdx.x], cs[threadIdx.x]);
    if (threadIdx.x == 0)   atomicAdd(&g_S, ss);
}

__global__ void k_bw() {
    __shared__ float part[4];
    int t = threadIdx.x;
    float v = g_v[t];
    float vv = v * v;
    #pragma unroll
    for (int o = 16; o; o >>= 1) vv += __shfl_xor_sync(0xffffffffu, vv, o);
    if ((t & 31) == 0) part[t >> 5] = vv;
    __syncthreads();
    if (t == 0) {
        double V = (double)part[0] + part[1] + part[2] + part[3];
        double sumL2 = 2.0 * (double)MTOT * (double)g_S - 2.0 * V;
        double bw = sumL2 / ((double)MTOT * (double)MTOT - (double)MTOT);
        bw *= 0.25;                               // / KERNEL_MUL^(5//2)
        double c = 1.0 / (16.0 * bw);
        g_c2l = (float)(c * 1.4426950408889634);  // exp2 form
    }
}

extern __shared__ float dsmem[];

__global__ void __launch_bounds__(256, 1)
k_main(const float* __restrict__ src, const float* __restrict__ tgt) {
    float* As = dsmem;                     // [k][m], row stride LDA
    float* Bs = dsmem + DDIM * LDA;        // [k][n_permuted]
    __shared__ float sqA[BM], nB[BN];
    __shared__ float red[8];

    int tid = threadIdx.x;
    int wid = tid >> 5, lane = tid & 31;

    // linear -> upper-triangle (bi, bj); tiles before row i: i*(129-i)/2
    int l = blockIdx.x;
    int bi = (int)((129.0 - sqrt(16641.0 - 8.0 * (double)l)) * 0.5);
    while ((bi + 1) * (129 - (bi + 1)) / 2 <= l) bi++;
    while (bi * (129 - bi) / 2 > l) bi--;
    int bj = bi + (l - bi * (129 - bi) / 2);

    int row0 = bi * BM, col0 = bj * BN;
    const float* Abase = (row0 < NHALF) ? (src + (size_t)row0 * DDIM)
                                        : (tgt + (size_t)(row0 - NHALF) * DDIM);
    const float* Bbase = (col0 < NHALF) ? (src + (size_t)col0 * DDIM)
                                        : (tgt + (size_t)(col0 - NHALF) * DDIM);

    float c2l = g_c2l;

    // Stage transposed tiles. A: plain As[k][m] (reads are broadcast).
    // B: permute n-chunks so reads are contiguous-16B per lane (conflict-free):
    //    chunk c (4 floats) -> phys chunk (c&1)*16 + (c>>1).
    #pragma unroll 8
    for (int i = 0; i < 64; i++) {
        int idx = tid + i * 256;           // 0..16383
        int k = idx & (DDIM - 1);
        int m = idx >> 7;
        As[k * LDA + m] = Abase[m * DDIM + k];
        int c = m >> 2;
        int np = (((c & 1) << 4) | (c >> 1)) * 4 + (m & 3);
        Bs[k * LDA + np] = Bbase[m * DDIM + k];
    }
    if (tid < BM)            sqA[tid]     = g_sq[row0 + tid];
    else                     nB[tid - BM] = -c2l * g_sq[col0 + tid - BM];
    __syncthreads();

    int ty = tid >> 4, tx = tid & 15;
    int m0 = ty * TM;

    u64 acc[TM][TN / 2];
    #pragma unroll
    for (int i = 0; i < TM; i++)
        #pragma unroll
        for (int j = 0; j < TN / 2; j++) acc[i][j] = 0ull;

    #pragma unroll 2
    for (int k = 0; k < DDIM; k++) {
        const float* ar = &As[k * LDA];
        const float* br = &Bs[k * LDA];
        // b: two conflict-free LDS.128 -> 4 packed f32x2 pairs covering n0..n0+7
        ulonglong2 bp0 = *(const ulonglong2*)(br + tx * 4);        // n0, n0+1 | n0+2, n0+3
        ulonglong2 bp1 = *(const ulonglong2*)(br + 64 + tx * 4);   // n0+4..n0+7
        u64 b2[4] = {bp0.x, bp0.y, bp1.x, bp1.y};
        // a: broadcast LDS.128 x2, then duplicate into pairs
        float4 a0 = *(const float4*)(ar + m0);
        float4 a1 = *(const float4*)(ar + m0 + 4);
        float a[TM] = {a0.x,a0.y,a0.z,a0.w,a1.x,a1.y,a1.z,a1.w};
        #pragma unroll
        for (int i = 0; i < TM; i++) {
            u64 ai = dup2(a[i]);
            #pragma unroll
            for (int j = 0; j < TN / 2; j++)
                ffma2(acc[i][j], ai, b2[j]);
        }
    }

    // Epilogue: 1 exp2 + repeated squaring for the 5-kernel sum
    int n0 = tx * TN;
    float tc2 = 2.0f * c2l;
    float lsum = 0.f;
    #pragma unroll
    for (int i = 0; i < TM; i++) {
        float ea = c2l * sqA[m0 + i];
        #pragma unroll
        for (int j = 0; j < TN / 2; j++) {
            float g0, g1;
            unpack2(g0, g1, acc[i][j]);
            float x0 = fmaf(tc2, g0, nB[n0 + 2*j]     - ea);   // = -c2l*L2
            float x1 = fmaf(tc2, g1, nB[n0 + 2*j + 1] - ea);
            float t  = exp2f(x0);
            float u  = exp2f(x1);
            float t2 = t*t, t4 = t2*t2, t8 = t4*t4, t16 = t8*t8;
            float u2 = u*u, u4 = u2*u2, u8 = u4*u4, u16 = u8*u8;
            lsum += ((t + t2) + (t4 + t8)) + t16;
            lsum += ((u + u2) + (u4 + u8)) + u16;
        }
    }

    float si = (bi < 32) ? 1.f : -1.f;
    float sj = (bj < 32) ? 1.f : -1.f;
    lsum *= si * sj * ((bi == bj) ? 1.f : 2.f);

    #pragma unroll
    for (int o = 16; o; o >>= 1) lsum += __shfl_xor_sync(0xffffffffu, lsum, o);
    if (lane == 0) red[wid] = lsum;
    __syncthreads();
    if (tid == 0) {
        float b = 0.f;
        #pragma unroll
        for (int wi = 0; wi < 8; wi++) b += red[wi];
        atomicAdd(&g_acc, (double)b);      // double: cross-tile cancellation
    }
}

__global__ void k_final(float* out) {
    out[0] = (float)(g_acc * (1.0 / ((double)NHALF * (double)NHALF)));
}

extern "C" void kernel_launch(void* const* d_in, const int* in_sizes, int n_in,
                              void* d_out, int out_size) {
    const float* src = (const float*)d_in[0];
    const float* tgt = (const float*)d_in[1];
    float* out = (float*)d_out;

    cudaFuncSetAttribute(k_main, cudaFuncAttributeMaxDynamicSharedMemorySize, SMEM_BYTES);

    k_init<<<1, 128>>>();
    k_rows<<<MTOT / 8, 256>>>(src, tgt);
    k_bw<<<1, 128>>>();
    k_main<<<NBLOCKS, 256, SMEM_BYTES>>>(src, tgt);
    k_final<<<1, 1>>>(out);
}

// round 8
// speedup vs baseline: 1.6333x; 1.6333x over previous
#include <cuda_runtime.h>
#include <math.h>
#include <cstdint>

#define MTOT 8192
#define NHALF 4096
#define DDIM 128
#define BM 128
#define BN 128
#define NBLOCKS 2080            // 64*65/2 upper-triangle tiles
#define LDA 132                 // smem row stride in floats (528B: ldmatrix conflict-free)
#define SMEM_BYTES (2 * DDIM * LDA * 4)

__device__ float  g_sq[MTOT];
__device__ float  g_v[DDIM];
__device__ float  g_S;
__device__ float  g_c2l;        // c*log2(e): t = exp(-c*L2) = exp2(-c2l*L2)
__device__ double g_acc;

// ---------------- helpers ----------------
__device__ __forceinline__ uint32_t smem_u32(const void* p) {
    uint32_t a;
    asm("{ .reg .u64 t; cvta.to.shared.u64 t, %1; cvt.u32.u64 %0, t; }" : "=r"(a) : "l"(p));
    return a;
}
__device__ __forceinline__ float to_tf32(float x) {
    float r;
    asm("cvt.rna.tf32.f32 %0, %1;" : "=f"(r) : "f"(x));
    return r;
}
__device__ __forceinline__ void ldsm4(uint32_t& r0, uint32_t& r1, uint32_t& r2, uint32_t& r3,
                                      uint32_t addr) {
    asm volatile("ldmatrix.sync.aligned.m8n8.x4.shared.b16 {%0,%1,%2,%3}, [%4];"
                 : "=r"(r0), "=r"(r1), "=r"(r2), "=r"(r3) : "r"(addr));
}
__device__ __forceinline__ void mma_tf32(float* d, const uint32_t* a, const uint32_t* b) {
    asm volatile(
        "mma.sync.aligned.m16n8k8.row.col.f32.tf32.tf32.f32 "
        "{%0,%1,%2,%3}, {%4,%5,%6,%7}, {%8,%9}, {%0,%1,%2,%3};"
        : "+f"(d[0]), "+f"(d[1]), "+f"(d[2]), "+f"(d[3])
        : "r"(a[0]), "r"(a[1]), "r"(a[2]), "r"(a[3]), "r"(b[0]), "r"(b[1]));
}

// ---------------- prep kernels (proven) ----------------
__global__ void k_init() {
    int t = threadIdx.x;
    if (t < DDIM) g_v[t] = 0.f;
    if (t == 0) { g_S = 0.f; g_acc = 0.0; }
}

__global__ void k_rows(const float* __restrict__ src, const float* __restrict__ tgt) {
    __shared__ float cs[DDIM];
    __shared__ float ss;
    int warp = threadIdx.x >> 5, lane = threadIdx.x & 31;
    int row = blockIdx.x * 8 + warp;
    const float* p = (row < NHALF) ? (src + (size_t)row * DDIM)
                                   : (tgt + (size_t)(row - NHALF) * DDIM);
    float4 x = ((const float4*)p)[lane];
    float s = x.x*x.x + x.y*x.y + x.z*x.z + x.w*x.w;
    if (threadIdx.x < DDIM) cs[threadIdx.x] = 0.f;
    if (threadIdx.x == 0) ss = 0.f;
    __syncthreads();
    atomicAdd(&cs[lane*4+0], x.x); atomicAdd(&cs[lane*4+1], x.y);
    atomicAdd(&cs[lane*4+2], x.z); atomicAdd(&cs[lane*4+3], x.w);
    #pragma unroll
    for (int o = 16; o; o >>= 1) s += __shfl_xor_sync(0xffffffffu, s, o);
    if (lane == 0) { g_sq[row] = s; atomicAdd(&ss, s); }
    __syncthreads();
    if (threadIdx.x < DDIM) atomicAdd(&g_v[threadIdx.x], cs[threadIdx.x]);
    if (threadIdx.x == 0)   atomicAdd(&g_S, ss);
}

__global__ void k_bw() {
    __shared__ float part[4];
    int t = threadIdx.x;
    float v = g_v[t];
    float vv = v * v;
    #pragma unroll
    for (int o = 16; o; o >>= 1) vv += __shfl_xor_sync(0xffffffffu, vv, o);
    if ((t & 31) == 0) part[t >> 5] = vv;
    __syncthreads();
    if (t == 0) {
        double V = (double)part[0] + part[1] + part[2] + part[3];
        double sumL2 = 2.0 * (double)MTOT * (double)g_S - 2.0 * V;
        double bw = sumL2 / ((double)MTOT * (double)MTOT - (double)MTOT);
        bw *= 0.25;
        double c = 1.0 / (16.0 * bw);
        g_c2l = (float)(c * 1.4426950408889634);
    }
}

// ---------------- main: TF32 mma.sync tile kernel ----------------
extern __shared__ float dsmem[];

__global__ void __launch_bounds__(256, 1)
k_main(const float* __restrict__ src, const float* __restrict__ tgt) {
    float* As = dsmem;                  // [m 0..127][k 0..127], stride LDA
    float* Bs = dsmem + DDIM * LDA;     // [n 0..127][k 0..127], stride LDA
    __shared__ float sqA[BM], nB[BN];
    __shared__ float red[8];

    int tid = threadIdx.x;
    int wid = tid >> 5, lane = tid & 31;

    // linear -> upper-triangle (bi, bj)
    int l = blockIdx.x;
    int bi = (int)((129.0 - sqrt(16641.0 - 8.0 * (double)l)) * 0.5);
    while ((bi + 1) * (129 - (bi + 1)) / 2 <= l) bi++;
    while (bi * (129 - bi) / 2 > l) bi--;
    int bj = bi + (l - bi * (129 - bi) / 2);

    int row0 = bi * BM, col0 = bj * BN;
    const float* Abase = (row0 < NHALF) ? (src + (size_t)row0 * DDIM)
                                        : (tgt + (size_t)(row0 - NHALF) * DDIM);
    const float* Bbase = (col0 < NHALF) ? (src + (size_t)col0 * DDIM)
                                        : (tgt + (size_t)(col0 - NHALF) * DDIM);

    float c2l = g_c2l;

    // Stage row-major tiles with tf32 rounding (cvt.rna) applied at store.
    #pragma unroll
    for (int i = 0; i < 16; i++) {
        int idx = tid + i * 256;         // float4 index 0..4095
        int r = idx >> 5;                // row 0..127
        int q = idx & 31;                // float4 within row
        float4 a = ((const float4*)Abase)[idx];
        float4 b = ((const float4*)Bbase)[idx];
        a.x = to_tf32(a.x); a.y = to_tf32(a.y); a.z = to_tf32(a.z); a.w = to_tf32(a.w);
        b.x = to_tf32(b.x); b.y = to_tf32(b.y); b.z = to_tf32(b.z); b.w = to_tf32(b.w);
        *(float4*)(As + r * LDA + q * 4) = a;
        *(float4*)(Bs + r * LDA + q * 4) = b;
    }
    if (tid < BM)            sqA[tid]     = g_sq[row0 + tid];
    else                     nB[tid - BM] = -c2l * g_sq[col0 + tid - BM];
    __syncthreads();

    // Warp tiling: 2 (m) x 4 (n) warps; warp tile 64x32 = 4 m-atoms x 4 n-atoms
    int wm = wid & 1, wn = wid >> 1;
    int m0 = wm * 64, n0 = wn * 32;

    float acc[4][4][4];
    #pragma unroll
    for (int a = 0; a < 4; a++)
        #pragma unroll
        for (int b = 0; b < 4; b++)
            #pragma unroll
            for (int r = 0; r < 4; r++) acc[a][b][r] = 0.f;

    // ldmatrix lane-address setup.
    // A atom a (x4 tiles): row = m0+16a + (lane&7) + 8*((lane>>3)&1), col = 4*(lane>>4)
    // B pair b2 (x4 tiles -> 2 n-atoms): row = n0+16*b2 + (lane&7) + 8*(lane>>4),
    //                                    col = 4*((lane>>3)&1)
    uint32_t a_addr[4], b_addr[2];
    {
        int ar = (lane & 7) + 8 * ((lane >> 3) & 1);
        int ac = 4 * (lane >> 4);
        #pragma unroll
        for (int a = 0; a < 4; a++)
            a_addr[a] = smem_u32(As + (m0 + 16 * a + ar) * LDA + ac);
        int br = (lane & 7) + 8 * (lane >> 4);
        int bc = 4 * ((lane >> 3) & 1);
        #pragma unroll
        for (int b = 0; b < 2; b++)
            b_addr[b] = smem_u32(Bs + (n0 + 16 * b + br) * LDA + bc);
    }

    #pragma unroll
    for (int s = 0; s < 16; s++) {
        uint32_t af[4][4], bf[2][4];
        #pragma unroll
        for (int a = 0; a < 4; a++)
            ldsm4(af[a][0], af[a][1], af[a][2], af[a][3], a_addr[a] + s * 32);
        #pragma unroll
        for (int b = 0; b < 2; b++)
            ldsm4(bf[b][0], bf[b][1], bf[b][2], bf[b][3], b_addr[b] + s * 32);
        // bf[b2] regs: {r0,r1} = n-atom 2*b2 (b0,b1); {r2,r3} = n-atom 2*b2+1
        #pragma unroll
        for (int a = 0; a < 4; a++) {
            #pragma unroll
            for (int b2 = 0; b2 < 2; b2++) {
                mma_tf32(acc[a][2 * b2],     af[a], &bf[b2][0]);
                mma_tf32(acc[a][2 * b2 + 1], af[a], &bf[b2][2]);
            }
        }
    }

    // Epilogue: atom (a,b): c0=(g, 2t), c1=(g, 2t+1), c2=(g+8, 2t), c3=(g+8, 2t+1)
    int g = lane >> 2, t2 = (lane & 3) * 2;
    float tc2 = 2.0f * c2l;
    float lsum = 0.f;
    #pragma unroll
    for (int a = 0; a < 4; a++) {
        float ea0 = c2l * sqA[m0 + 16 * a + g];
        float ea1 = c2l * sqA[m0 + 16 * a + g + 8];
        #pragma unroll
        for (int b = 0; b < 4; b++) {
            float nb0 = nB[n0 + 8 * b + t2];
            float nb1 = nB[n0 + 8 * b + t2 + 1];
            float x0 = fmaf(tc2, acc[a][b][0], nb0 - ea0);
            float x1 = fmaf(tc2, acc[a][b][1], nb1 - ea0);
            float x2 = fmaf(tc2, acc[a][b][2], nb0 - ea1);
            float x3 = fmaf(tc2, acc[a][b][3], nb1 - ea1);
            float p0 = exp2f(x0), p1 = exp2f(x1), p2 = exp2f(x2), p3 = exp2f(x3);
            float q0 = p0*p0, q1 = p1*p1, q2 = p2*p2, q3 = p3*p3;
            float r0 = q0*q0, r1 = q1*q1, r2 = q2*q2, r3 = q3*q3;
            float s0 = r0*r0, s1 = r1*r1, s2 = r2*r2, s3 = r3*r3;
            float w0 = s0*s0, w1 = s1*s1, w2 = s2*s2, w3 = s3*s3;
            lsum += ((p0 + q0) + (r0 + s0)) + w0;
            lsum += ((p1 + q1) + (r1 + s1)) + w1;
            lsum += ((p2 + q2) + (r2 + s2)) + w2;
            lsum += ((p3 + q3) + (r3 + s3)) + w3;
        }
    }

    float si = (bi < 32) ? 1.f : -1.f;
    float sj = (bj < 32) ? 1.f : -1.f;
    lsum *= si * sj * ((bi == bj) ? 1.f : 2.f);

    #pragma unroll
    for (int o = 16; o; o >>= 1) lsum += __shfl_xor_sync(0xffffffffu, lsum, o);
    if (lane == 0) red[wid] = lsum;
    __syncthreads();
    if (tid == 0) {
        float b = 0.f;
        #pragma unroll
        for (int wi = 0; wi < 8; wi++) b += red[wi];
        atomicAdd(&g_acc, (double)b);    // double: cross-tile cancellation
    }
}

__global__ void k_final(float* out) {
    out[0] = (float)(g_acc * (1.0 / ((double)NHALF * (double)NHALF)));
}

extern "C" void kernel_launch(void* const* d_in, const int* in_sizes, int n_in,
                              void* d_out, int out_size) {
    const float* src = (const float*)d_in[0];
    const float* tgt = (const float*)d_in[1];
    float* out = (float*)d_out;

    cudaFuncSetAttribute(k_main, cudaFuncAttributeMaxDynamicSharedMemorySize, SMEM_BYTES);

    k_init<<<1, 128>>>();
    k_rows<<<MTOT / 8, 256>>>(src, tgt);
    k_bw<<<1, 128>>>();
    k_main<<<NBLOCKS, 256, SMEM_BYTES>>>(src, tgt);
    k_final<<<1, 1>>>(out);
}

// round 9
// speedup vs baseline: 3.9142x; 2.3965x over previous
#include <cuda_runtime.h>
#include <cuda_fp16.h>
#include <math.h>
#include <cstdint>

#define MTOT 8192
#define NHALF 4096
#define DDIM 128
#define BM 128
#define BN 128
#define NBLOCKS 2080            // 64*65/2 upper-triangle tiles
#define LDH 136                 // smem row stride in halves (272B: ldmatrix conflict-free)
#define SMEM_BYTES (2 * DDIM * LDH * 2)

__device__ float  g_sq[MTOT];
__device__ float  g_v[DDIM];
__device__ float  g_S;
__device__ float  g_c2l;        // c*log2(e): t = exp(-c*L2) = exp2(-c2l*L2)
__device__ double g_acc;

// ---------------- helpers ----------------
__device__ __forceinline__ uint32_t smem_u32(const void* p) {
    uint32_t a;
    asm("{ .reg .u64 t; cvta.to.shared.u64 t, %1; cvt.u32.u64 %0, t; }" : "=r"(a) : "l"(p));
    return a;
}
__device__ __forceinline__ void ldsm4(uint32_t& r0, uint32_t& r1, uint32_t& r2, uint32_t& r3,
                                      uint32_t addr) {
    asm volatile("ldmatrix.sync.aligned.m8n8.x4.shared.b16 {%0,%1,%2,%3}, [%4];"
                 : "=r"(r0), "=r"(r1), "=r"(r2), "=r"(r3) : "r"(addr));
}
__device__ __forceinline__ void mma_f16(float* d, const uint32_t* a,
                                        uint32_t b0, uint32_t b1) {
    asm volatile(
        "mma.sync.aligned.m16n8k16.row.col.f32.f16.f16.f32 "
        "{%0,%1,%2,%3}, {%4,%5,%6,%7}, {%8,%9}, {%0,%1,%2,%3};"
        : "+f"(d[0]), "+f"(d[1]), "+f"(d[2]), "+f"(d[3])
        : "r"(a[0]), "r"(a[1]), "r"(a[2]), "r"(a[3]), "r"(b0), "r"(b1));
}

// ---------------- prep kernels (proven) ----------------
__global__ void k_init() {
    int t = threadIdx.x;
    if (t < DDIM) g_v[t] = 0.f;
    if (t == 0) { g_S = 0.f; g_acc = 0.0; }
}

__global__ void k_rows(const float* __restrict__ src, const float* __restrict__ tgt) {
    __shared__ float cs[DDIM];
    __shared__ float ss;
    int warp = threadIdx.x >> 5, lane = threadIdx.x & 31;
    int row = blockIdx.x * 8 + warp;
    const float* p = (row < NHALF) ? (src + (size_t)row * DDIM)
                                   : (tgt + (size_t)(row - NHALF) * DDIM);
    float4 x = ((const float4*)p)[lane];
    float s = x.x*x.x + x.y*x.y + x.z*x.z + x.w*x.w;
    if (threadIdx.x < DDIM) cs[threadIdx.x] = 0.f;
    if (threadIdx.x == 0) ss = 0.f;
    __syncthreads();
    atomicAdd(&cs[lane*4+0], x.x); atomicAdd(&cs[lane*4+1], x.y);
    atomicAdd(&cs[lane*4+2], x.z); atomicAdd(&cs[lane*4+3], x.w);
    #pragma unroll
    for (int o = 16; o; o >>= 1) s += __shfl_xor_sync(0xffffffffu, s, o);
    if (lane == 0) { g_sq[row] = s; atomicAdd(&ss, s); }
    __syncthreads();
    if (threadIdx.x < DDIM) atomicAdd(&g_v[threadIdx.x], cs[threadIdx.x]);
    if (threadIdx.x == 0)   atomicAdd(&g_S, ss);
}

__global__ void k_bw() {
    __shared__ float part[4];
    int t = threadIdx.x;
    float v = g_v[t];
    float vv = v * v;
    #pragma unroll
    for (int o = 16; o; o >>= 1) vv += __shfl_xor_sync(0xffffffffu, vv, o);
    if ((t & 31) == 0) part[t >> 5] = vv;
    __syncthreads();
    if (t == 0) {
        double V = (double)part[0] + part[1] + part[2] + part[3];
        double sumL2 = 2.0 * (double)MTOT * (double)g_S - 2.0 * V;
        double bw = sumL2 / ((double)MTOT * (double)MTOT - (double)MTOT);
        bw *= 0.25;
        double c = 1.0 / (16.0 * bw);
        g_c2l = (float)(c * 1.4426950408889634);
    }
}

// ---------------- main: fp16 mma.sync tile kernel, 2 CTAs/SM ----------------
extern __shared__ __half dsmh[];

__global__ void __launch_bounds__(256, 2)
k_main(const float* __restrict__ src, const float* __restrict__ tgt) {
    __half* As = dsmh;                  // [m 0..127][k 0..127], stride LDH halves
    __half* Bs = dsmh + DDIM * LDH;     // [n 0..127][k 0..127]
    __shared__ float sqA[BM], nB[BN];
    __shared__ float red[8];

    int tid = threadIdx.x;
    int wid = tid >> 5, lane = tid & 31;

    // linear -> upper-triangle (bi, bj)
    int l = blockIdx.x;
    int bi = (int)((129.0 - sqrt(16641.0 - 8.0 * (double)l)) * 0.5);
    while ((bi + 1) * (129 - (bi + 1)) / 2 <= l) bi++;
    while (bi * (129 - bi) / 2 > l) bi--;
    int bj = bi + (l - bi * (129 - bi) / 2);

    int row0 = bi * BM, col0 = bj * BN;
    const float* Abase = (row0 < NHALF) ? (src + (size_t)row0 * DDIM)
                                        : (tgt + (size_t)(row0 - NHALF) * DDIM);
    const float* Bbase = (col0 < NHALF) ? (src + (size_t)col0 * DDIM)
                                        : (tgt + (size_t)(col0 - NHALF) * DDIM);

    float c2l = g_c2l;

    // Stage row-major half tiles (rn conversion at store).
    #pragma unroll
    for (int i = 0; i < 16; i++) {
        int idx = tid + i * 256;         // float4 index 0..4095
        int r = idx >> 5;                // row 0..127
        int q = idx & 31;                // float4 (-> 4 halves) within row
        float4 a = ((const float4*)Abase)[idx];
        float4 b = ((const float4*)Bbase)[idx];
        union { __half2 h[2]; uint2 u; } pa, pb;
        pa.h[0] = __floats2half2_rn(a.x, a.y);
        pa.h[1] = __floats2half2_rn(a.z, a.w);
        pb.h[0] = __floats2half2_rn(b.x, b.y);
        pb.h[1] = __floats2half2_rn(b.z, b.w);
        *(uint2*)(As + r * LDH + q * 4) = pa.u;
        *(uint2*)(Bs + r * LDH + q * 4) = pb.u;
    }
    if (tid < BM)            sqA[tid]     = g_sq[row0 + tid];
    else                     nB[tid - BM] = -c2l * g_sq[col0 + tid - BM];
    __syncthreads();

    // Warp tiling: 2 (m) x 4 (n) warps; warp tile 64x32 = 4 m-atoms(16) x 4 n-atoms(8)
    int wm = wid & 1, wn = wid >> 1;
    int m0 = wm * 64, n0 = wn * 32;

    float acc[4][4][4];
    #pragma unroll
    for (int a = 0; a < 4; a++)
        #pragma unroll
        for (int b = 0; b < 4; b++)
            #pragma unroll
            for (int r = 0; r < 4; r++) acc[a][b][r] = 0.f;

    // ldmatrix addresses (identical pattern for A and B, k16 atoms):
    // row = base + (lane&15), col = 8*(lane>>4) halves; advance +32B per k-step.
    uint32_t a_addr[4], b_addr[2];
    {
        int rr = lane & 15;
        int cc = 8 * (lane >> 4);
        #pragma unroll
        for (int a = 0; a < 4; a++)
            a_addr[a] = smem_u32(As + (m0 + 16 * a + rr) * LDH + cc);
        #pragma unroll
        for (int b = 0; b < 2; b++)
            b_addr[b] = smem_u32(Bs + (n0 + 16 * b + rr) * LDH + cc);
    }

    #pragma unroll
    for (int s = 0; s < 8; s++) {
        uint32_t af[4][4], bf[2][4];
        #pragma unroll
        for (int a = 0; a < 4; a++)
            ldsm4(af[a][0], af[a][1], af[a][2], af[a][3], a_addr[a] + s * 32);
        #pragma unroll
        for (int b = 0; b < 2; b++)
            ldsm4(bf[b][0], bf[b][1], bf[b][2], bf[b][3], b_addr[b] + s * 32);
        // bf[g]: n-atom 2g   uses {r0, r2} (k0-7, k8-15), n-atom 2g+1 uses {r1, r3}
        #pragma unroll
        for (int a = 0; a < 4; a++) {
            #pragma unroll
            for (int g2 = 0; g2 < 2; g2++) {
                mma_f16(acc[a][2 * g2],     af[a], bf[g2][0], bf[g2][2]);
                mma_f16(acc[a][2 * g2 + 1], af[a], bf[g2][1], bf[g2][3]);
            }
        }
    }

    // Epilogue: atom (a,b): c0=(g,2t), c1=(g,2t+1), c2=(g+8,2t), c3=(g+8,2t+1)
    int g = lane >> 2, t2 = (lane & 3) * 2;
    float tc2 = 2.0f * c2l;
    float lsum = 0.f;
    #pragma unroll
    for (int a = 0; a < 4; a++) {
        float ea0 = c2l * sqA[m0 + 16 * a + g];
        float ea1 = c2l * sqA[m0 + 16 * a + g + 8];
        #pragma unroll
        for (int b = 0; b < 4; b++) {
            float nb0 = nB[n0 + 8 * b + t2];
            float nb1 = nB[n0 + 8 * b + t2 + 1];
            float base[4] = {nb0 - ea0, nb1 - ea0, nb0 - ea1, nb1 - ea1};
            #pragma unroll
            for (int v = 0; v < 4; v++) {
                float x = fmaf(tc2, acc[a][b][v], base[v]);  // = -c2l*L2
                float t  = exp2f(x);
                float t2v = t * t, t4 = t2v * t2v, t8 = t4 * t4;
                lsum += ((t + t2v) + (t4 + t8)) + t8 * t8;
            }
        }
    }

    float si = (bi < 32) ? 1.f : -1.f;
    float sj = (bj < 32) ? 1.f : -1.f;
    lsum *= si * sj * ((bi == bj) ? 1.f : 2.f);

    #pragma unroll
    for (int o = 16; o; o >>= 1) lsum += __shfl_xor_sync(0xffffffffu, lsum, o);
    if (lane == 0) red[wid] = lsum;
    __syncthreads();
    if (tid == 0) {
        float b = 0.f;
        #pragma unroll
        for (int wi = 0; wi < 8; wi++) b += red[wi];
        atomicAdd(&g_acc, (double)b);    // double: cross-tile cancellation
    }
}

__global__ void k_final(float* out) {
    out[0] = (float)(g_acc * (1.0 / ((double)NHALF * (double)NHALF)));
}

extern "C" void kernel_launch(void* const* d_in, const int* in_sizes, int n_in,
                              void* d_out, int out_size) {
    const float* src = (const float*)d_in[0];
    const float* tgt = (const float*)d_in[1];
    float* out = (float*)d_out;

    cudaFuncSetAttribute(k_main, cudaFuncAttributeMaxDynamicSharedMemorySize, SMEM_BYTES);

    k_init<<<1, 128>>>();
    k_rows<<<MTOT / 8, 256>>>(src, tgt);
    k_bw<<<1, 128>>>();
    k_main<<<NBLOCKS, 256, SMEM_BYTES>>>(src, tgt);
    k_final<<<1, 1>>>(out);
}

// round 10
// speedup vs baseline: 4.1731x; 1.0661x over previous
#include <cuda_runtime.h>
#include <cuda_fp16.h>
#include <math.h>
#include <cstdint>

#define MTOT 8192
#define NHALF 4096
#define DDIM 128
#define BM 128
#define BN 128
#define NBLOCKS 2080            // 64*65/2 upper-triangle tiles
#define LDH 136                 // smem row stride in halves (272B: ldmatrix conflict-free)
#define SMEM_BYTES (2 * DDIM * LDH * 2)

__device__ __half g_half[MTOT * DDIM];   // fp16 copy of [src; tgt] (2MB scratch)
__device__ float  g_sq[MTOT];
__device__ float  g_v[DDIM];             // zero-init at load; reset by k_final
__device__ float  g_S = 0.f;
__device__ float  g_c2l = 0.f;           // c*log2(e): t = exp(-c*L2) = exp2(-c2l*L2)
__device__ double g_acc = 0.0;

// ---------------- helpers ----------------
__device__ __forceinline__ uint32_t smem_u32(const void* p) {
    uint32_t a;
    asm("{ .reg .u64 t; cvta.to.shared.u64 t, %1; cvt.u32.u64 %0, t; }" : "=r"(a) : "l"(p));
    return a;
}
__device__ __forceinline__ void cp16(uint32_t s, const void* g) {
    asm volatile("cp.async.cg.shared.global [%0], [%1], 16;" :: "r"(s), "l"(g));
}
__device__ __forceinline__ void ldsm4(uint32_t& r0, uint32_t& r1, uint32_t& r2, uint32_t& r3,
                                      uint32_t addr) {
    asm volatile("ldmatrix.sync.aligned.m8n8.x4.shared.b16 {%0,%1,%2,%3}, [%4];"
                 : "=r"(r0), "=r"(r1), "=r"(r2), "=r"(r3) : "r"(addr));
}
__device__ __forceinline__ void mma_f16(float* d, const uint32_t* a,
                                        uint32_t b0, uint32_t b1) {
    asm volatile(
        "mma.sync.aligned.m16n8k16.row.col.f32.f16.f16.f32 "
        "{%0,%1,%2,%3}, {%4,%5,%6,%7}, {%8,%9}, {%0,%1,%2,%3};"
        : "+f"(d[0]), "+f"(d[1]), "+f"(d[2]), "+f"(d[3])
        : "r"(a[0]), "r"(a[1]), "r"(a[2]), "r"(a[3]), "r"(b0), "r"(b1));
}

// ---------------- prep: row norms + col sums + fp16 convert (one pass) ----------------
__global__ void k_rows(const float* __restrict__ src, const float* __restrict__ tgt) {
    __shared__ float cs[DDIM];
    __shared__ float ss;
    int warp = threadIdx.x >> 5, lane = threadIdx.x & 31;
    int row = blockIdx.x * 8 + warp;
    const float* p = (row < NHALF) ? (src + (size_t)row * DDIM)
                                   : (tgt + (size_t)(row - NHALF) * DDIM);
    float4 x = ((const float4*)p)[lane];

    // fp16 convert + store (coalesced 8B/lane)
    union { __half2 h[2]; uint2 u; } ph;
    ph.h[0] = __floats2half2_rn(x.x, x.y);
    ph.h[1] = __floats2half2_rn(x.z, x.w);
    ((uint2*)(g_half + (size_t)row * DDIM))[lane] = ph.u;

    float s = x.x*x.x + x.y*x.y + x.z*x.z + x.w*x.w;
    if (threadIdx.x < DDIM) cs[threadIdx.x] = 0.f;
    if (threadIdx.x == 0) ss = 0.f;
    __syncthreads();
    atomicAdd(&cs[lane*4+0], x.x); atomicAdd(&cs[lane*4+1], x.y);
    atomicAdd(&cs[lane*4+2], x.z); atomicAdd(&cs[lane*4+3], x.w);
    #pragma unroll
    for (int o = 16; o; o >>= 1) s += __shfl_xor_sync(0xffffffffu, s, o);
    if (lane == 0) { g_sq[row] = s; atomicAdd(&ss, s); }
    __syncthreads();
    if (threadIdx.x < DDIM) atomicAdd(&g_v[threadIdx.x], cs[threadIdx.x]);
    if (threadIdx.x == 0)   atomicAdd(&g_S, ss);
}

__global__ void k_bw() {
    __shared__ float part[4];
    int t = threadIdx.x;
    float v = g_v[t];
    float vv = v * v;
    #pragma unroll
    for (int o = 16; o; o >>= 1) vv += __shfl_xor_sync(0xffffffffu, vv, o);
    if ((t & 31) == 0) part[t >> 5] = vv;
    __syncthreads();
    if (t == 0) {
        double V = (double)part[0] + part[1] + part[2] + part[3];
        double sumL2 = 2.0 * (double)MTOT * (double)g_S - 2.0 * V;
        double bw = sumL2 / ((double)MTOT * (double)MTOT - (double)MTOT);
        bw *= 0.25;
        double c = 1.0 / (16.0 * bw);
        g_c2l = (float)(c * 1.4426950408889634);
    }
}

// ---------------- main: fp16 mma.sync tile kernel, 2 CTAs/SM ----------------
extern __shared__ __half dsmh[];

__global__ void __launch_bounds__(256, 2)
k_main() {
    __half* As = dsmh;                  // [m 0..127][k 0..127], stride LDH halves
    __half* Bs = dsmh + DDIM * LDH;     // [n 0..127][k 0..127]
    __shared__ float sqA[BM], nB[BN];
    __shared__ float red[8];

    int tid = threadIdx.x;
    int wid = tid >> 5, lane = tid & 31;

    // linear -> upper-triangle (bi, bj)
    int l = blockIdx.x;
    int bi = (int)((129.0 - sqrt(16641.0 - 8.0 * (double)l)) * 0.5);
    while ((bi + 1) * (129 - (bi + 1)) / 2 <= l) bi++;
    while (bi * (129 - bi) / 2 > l) bi--;
    int bj = bi + (l - bi * (129 - bi) / 2);

    int row0 = bi * BM, col0 = bj * BN;
    const __half* Ab = g_half + (size_t)row0 * DDIM;
    const __half* Bb = g_half + (size_t)col0 * DDIM;

    float c2l = g_c2l;

    // Stage half tiles via cp.async: 2048 uint4 per tile, 8 per thread per tile.
    uint32_t as_base = smem_u32(As), bs_base = smem_u32(Bs);
    #pragma unroll
    for (int i = 0; i < 8; i++) {
        int idx = tid + i * 256;         // uint4 index 0..2047
        int r = idx >> 4;                // row 0..127
        int q = idx & 15;                // uint4 (8 halves) within row
        uint32_t soff = (uint32_t)(r * LDH + q * 8) * 2;
        cp16(as_base + soff, Ab + idx * 8);
        cp16(bs_base + soff, Bb + idx * 8);
    }
    asm volatile("cp.async.commit_group;" ::: "memory");
    if (tid < BM)            sqA[tid]     = g_sq[row0 + tid];
    else                     nB[tid - BM] = -c2l * g_sq[col0 + tid - BM];
    asm volatile("cp.async.wait_group 0;" ::: "memory");
    __syncthreads();

    // Warp tiling: 2 (m) x 4 (n) warps; warp tile 64x32 = 4 m-atoms(16) x 4 n-atoms(8)
    int wm = wid & 1, wn = wid >> 1;
    int m0 = wm * 64, n0 = wn * 32;

    float acc[4][4][4];
    #pragma unroll
    for (int a = 0; a < 4; a++)
        #pragma unroll
        for (int b = 0; b < 4; b++)
            #pragma unroll
            for (int r = 0; r < 4; r++) acc[a][b][r] = 0.f;

    // ldmatrix addresses (identical pattern for A and B, k16 atoms):
    // row = base + (lane&15), col = 8*(lane>>4) halves; advance +32B per k-step.
    uint32_t a_addr[4], b_addr[2];
    {
        int rr = lane & 15;
        int cc = 8 * (lane >> 4);
        #pragma unroll
        for (int a = 0; a < 4; a++)
            a_addr[a] = smem_u32(As + (m0 + 16 * a + rr) * LDH + cc);
        #pragma unroll
        for (int b = 0; b < 2; b++)
            b_addr[b] = smem_u32(Bs + (n0 + 16 * b + rr) * LDH + cc);
    }

    #pragma unroll
    for (int s = 0; s < 8; s++) {
        uint32_t af[4][4], bf[2][4];
        #pragma unroll
        for (int a = 0; a < 4; a++)
            ldsm4(af[a][0], af[a][1], af[a][2], af[a][3], a_addr[a] + s * 32);
        #pragma unroll
        for (int b = 0; b < 2; b++)
            ldsm4(bf[b][0], bf[b][1], bf[b][2], bf[b][3], b_addr[b] + s * 32);
        // bf[g]: n-atom 2g uses {r0, r2} (k0-7, k8-15); n-atom 2g+1 uses {r1, r3}
        #pragma unroll
        for (int a = 0; a < 4; a++) {
            #pragma unroll
            for (int g2 = 0; g2 < 2; g2++) {
                mma_f16(acc[a][2 * g2],     af[a], bf[g2][0], bf[g2][2]);
                mma_f16(acc[a][2 * g2 + 1], af[a], bf[g2][1], bf[g2][3]);
            }
        }
    }

    // Epilogue: atom (a,b): c0=(g,2t), c1=(g,2t+1), c2=(g+8,2t), c3=(g+8,2t+1)
    int g = lane >> 2, t2 = (lane & 3) * 2;
    float tc2 = 2.0f * c2l;
    float lsum = 0.f;
    #pragma unroll
    for (int a = 0; a < 4; a++) {
        float ea0 = c2l * sqA[m0 + 16 * a + g];
        float ea1 = c2l * sqA[m0 + 16 * a + g + 8];
        #pragma unroll
        for (int b = 0; b < 4; b++) {
            float nb0 = nB[n0 + 8 * b + t2];
            float nb1 = nB[n0 + 8 * b + t2 + 1];
            float base[4] = {nb0 - ea0, nb1 - ea0, nb0 - ea1, nb1 - ea1};
            #pragma unroll
            for (int v = 0; v < 4; v++) {
                float x = fmaf(tc2, acc[a][b][v], base[v]);  // = -c2l*L2
                float t   = exp2f(x);
                float t2v = t * t;
                float u   = t2v + t;                   // t + t^2
                float t4  = t2v * t2v;
                float t8  = t4 * t4;
                float w   = fmaf(t8, t8, t8);          // t^8 + t^16
                lsum += (u + t4) + w;
            }
        }
    }

    float si = (bi < 32) ? 1.f : -1.f;
    float sj = (bj < 32) ? 1.f : -1.f;
    lsum *= si * sj * ((bi == bj) ? 1.f : 2.f);

    #pragma unroll
    for (int o = 16; o; o >>= 1) lsum += __shfl_xor_sync(0xffffffffu, lsum, o);
    if (lane == 0) red[wid] = lsum;
    __syncthreads();
    if (tid == 0) {
        float b = 0.f;
        #pragma unroll
        for (int wi = 0; wi < 8; wi++) b += red[wi];
        atomicAdd(&g_acc, (double)b);    // double: cross-tile cancellation
    }
}

// output + reset accumulators so every graph replay starts from identical state
__global__ void k_final(float* out) {
    int t = threadIdx.x;
    if (t == 0) {
        out[0] = (float)(g_acc * (1.0 / ((double)NHALF * (double)NHALF)));
        g_acc = 0.0;
        g_S = 0.f;
    }
    if (t < DDIM) g_v[t] = 0.f;
}

extern "C" void kernel_launch(void* const* d_in, const int* in_sizes, int n_in,
                              void* d_out, int out_size) {
    const float* src = (const float*)d_in[0];
    const float* tgt = (const float*)d_in[1];
    float* out = (float*)d_out;

    cudaFuncSetAttribute(k_main, cudaFuncAttributeMaxDynamicSharedMemorySize, SMEM_BYTES);

    k_rows<<<MTOT / 8, 256>>>(src, tgt);
    k_bw<<<1, 128>>>();
    k_main<<<NBLOCKS, 256, SMEM_BYTES>>>();
    k_final<<<1, 128>>>(out);
}